// round 4
// baseline (speedup 1.0000x reference)
#include <cuda_runtime.h>
#include <math.h>

#define D 128
#define PAD 132            // smem row pitch (floats)
#define PADE 129
#define NMAX 65536
#define NSQ 10
#define NREF 5

static __device__ int   g_degi[NMAX];
static __device__ float g_dinv[NMAX];
static __device__ float g_p[NMAX];
static __device__ float g_sacc[NMAX];
static __device__ float g_scores[NMAX];
static __device__ float g_q[NMAX];
static __device__ __align__(16) float g_E1[(size_t)NMAX * D];   // 0.5*x@W1 + b1
static __device__ __align__(16) float g_G[D * D];
static __device__ __align__(16) float g_Ea[D * D];
static __device__ __align__(16) float g_Eb[D * D];
static __device__ float g_scale[16];
static __device__ float g_v1[D];
static __device__ float g_a1[D];
static __device__ float g_wv[D];
static __device__ float g_bg;
static __device__ int   g_i32;   // 1 => edge_index is int32, 0 => int64

// ---------------------------------------------------------------- utilities
__device__ __forceinline__ void load_edge(const void* ei, int E, int e, int& s, int& t) {
    if (g_i32) {
        const int* p = (const int*)ei;
        s = p[e]; t = p[E + e];
    } else {
        const long long* p = (const long long*)ei;
        s = (int)p[e]; t = (int)p[E + e];
    }
}

__device__ __forceinline__ float sigmoidf_(float z) {
    return 1.0f / (1.0f + expf(-z));
}

__device__ __forceinline__ unsigned smem_u32(const void* p) {
    return (unsigned)__cvta_generic_to_shared(p);
}
__device__ __forceinline__ void cp16(unsigned s, const void* g) {
    asm volatile("cp.async.cg.shared.global [%0], [%1], 16;\n" :: "r"(s), "l"(g));
}
#define CP_COMMIT() asm volatile("cp.async.commit_group;\n" ::)
#define CP_WAIT(n)  asm volatile("cp.async.wait_group %0;\n" :: "n"(n))

// ---------------------------------------------------------------- fused prologue
__global__ void k_pre(const long long* ei, int E, int N,
                      const float* __restrict__ wg, const float* __restrict__ bgc,
                      const float* __restrict__ ws, const float* __restrict__ bs, int ZB) {
    int b = blockIdx.x, t = threadIdx.x;
    if (b < ZB) {
        int i = b * 256 + t;
        if (i < N) g_degi[i] = 0;
        if (i < D * D) g_G[i] = 0.0f;
        if (i < 16) g_scale[i] = 0.0f;
    } else if (b == ZB) {
        __shared__ int flag;
        if (t == 0) flag = 0;
        __syncthreads();
        int n = E < 1024 ? E : 1024;
        for (int e = t; e < n; e += 256)
            if ((unsigned long long)ei[e] >= (unsigned long long)N) flag = 1;
        __syncthreads();
        if (t == 0) g_i32 = flag;
    } else {
        __shared__ float wss[D];
        if (t < D) wss[t] = ws[t];
        __syncthreads();
        if (t < D) {
            float s = 0.0f;
            #pragma unroll 8
            for (int m = 0; m < D; m++) s += wg[t * D + m] * wss[m];
            g_wv[t] = s;
        }
        if (t == 0) {
            float bsum = bs[0];
            for (int m = 0; m < D; m++) bsum += bgc[m] * wss[m];
            g_bg = bsum;
        }
    }
}

// ---------------------------------------------------------------- edge/score chain (stream s1)
__global__ void k_p(const float* __restrict__ x, int N) {
    int w = (blockIdx.x * blockDim.x + threadIdx.x) >> 5;
    int lane = threadIdx.x & 31;
    if (w >= N) return;
    float4 xv = ((const float4*)x)[(size_t)w * 32 + lane];
    float4 wv = *(const float4*)&g_wv[lane * 4];
    float s = xv.x * wv.x + xv.y * wv.y + xv.z * wv.z + xv.w * wv.w;
    #pragma unroll
    for (int o = 16; o; o >>= 1) s += __shfl_xor_sync(0xffffffffu, s, o);
    if (lane == 0) g_p[w] = s;
}

__global__ void k_deg(const void* ei, int E) {
    int e = blockIdx.x * 256 + threadIdx.x;
    if (e >= E) return;
    int t = g_i32 ? ((const int*)ei)[E + e] : (int)((const long long*)ei)[E + e];
    atomicAdd(&g_degi[t], 1);
}

__global__ void k_dinv(int N) {
    int i = blockIdx.x * 256 + threadIdx.x;
    if (i >= N) return;
    float di = rsqrtf((float)(g_degi[i] + 1));   // +1 = self loop
    g_dinv[i] = di;
    g_sacc[i] = di * di * g_p[i];
}

__global__ void k_edge(const void* ei, int E) {
    int e = blockIdx.x * 256 + threadIdx.x;
    if (e >= E) return;
    int s, t; load_edge(ei, E, e, s, t);
    atomicAdd(&g_sacc[t], g_dinv[s] * g_dinv[t] * g_p[s]);
}

__global__ void k_scores(int N) {
    int i = blockIdx.x * 256 + threadIdx.x;
    if (i >= N) return;
    g_scores[i] = sigmoidf_(g_sacc[i] + g_bg);
}

__global__ void k_gate(const void* ei, const float* __restrict__ ew,
                       const float* __restrict__ al, const float* __restrict__ be,
                       float* __restrict__ out, int E) {
    int e = blockIdx.x * 256 + threadIdx.x;
    if (e >= E) return;
    int s, t; load_edge(ei, E, e, s, t);
    float z = al[0] * (g_scores[s] + g_scores[t]) + be[0];
    out[e] = ew[e] * sigmoidf_(z);
}

// ---------------------------------------------------------------- Gram, cp.async double-buffered
__global__ __launch_bounds__(512, 1) void k_G(const float* __restrict__ x, int N, int nChunks) {
    extern __shared__ float sm[];
    float* bufs[2] = { sm, sm + 128 * PAD };
    int tid = threadIdx.x;
    int ty = tid >> 4, tx = tid & 15;
    int r0 = ty * 4, cA = tx * 4, cB = cA + 64;
    int stride = gridDim.x;

    float acc[4][8];
    #pragma unroll
    for (int i = 0; i < 4; i++)
        #pragma unroll
        for (int j = 0; j < 8; j++) acc[i][j] = 0.0f;

    int ch = blockIdx.x;
    if (ch < nChunks) {
        int R0 = ch * 128;
        if (R0 + 128 <= N) {
            #pragma unroll
            for (int u = 0; u < 8; u++) {
                int idx = tid + u * 512;
                int r = idx >> 5, c4 = idx & 31;
                cp16(smem_u32(&bufs[0][r * PAD + c4 * 4]), &x[((size_t)(R0 + r)) * 128 + c4 * 4]);
            }
        } else {
            #pragma unroll
            for (int u = 0; u < 8; u++) {
                int idx = tid + u * 512;
                int r = idx >> 5, c4 = idx & 31;
                int gr = R0 + r;
                float4 v = (gr < N) ? ((const float4*)x)[(size_t)gr * 32 + c4]
                                    : make_float4(0.f, 0.f, 0.f, 0.f);
                *(float4*)&bufs[0][r * PAD + c4 * 4] = v;
            }
        }
        CP_COMMIT();
    }

    int cur = 0;
    for (; ch < nChunks; ch += stride) {
        int nxt = ch + stride;
        if (nxt < nChunks) {
            float* bn = bufs[cur ^ 1];
            int R0 = nxt * 128;
            if (R0 + 128 <= N) {
                #pragma unroll
                for (int u = 0; u < 8; u++) {
                    int idx = tid + u * 512;
                    int r = idx >> 5, c4 = idx & 31;
                    cp16(smem_u32(&bn[r * PAD + c4 * 4]), &x[((size_t)(R0 + r)) * 128 + c4 * 4]);
                }
            } else {
                #pragma unroll
                for (int u = 0; u < 8; u++) {
                    int idx = tid + u * 512;
                    int r = idx >> 5, c4 = idx & 31;
                    int gr = R0 + r;
                    float4 v = (gr < N) ? ((const float4*)x)[(size_t)gr * 32 + c4]
                                        : make_float4(0.f, 0.f, 0.f, 0.f);
                    *(float4*)&bn[r * PAD + c4 * 4] = v;
                }
            }
            CP_COMMIT();
            CP_WAIT(1);
        } else {
            CP_WAIT(0);
        }
        __syncthreads();
        const float* bc = bufs[cur];
        #pragma unroll 4
        for (int k = 0; k < 128; k++) {
            float4 av = *(const float4*)&bc[k * PAD + r0];
            float4 b0 = *(const float4*)&bc[k * PAD + cA];
            float4 b1 = *(const float4*)&bc[k * PAD + cB];
            float a[4] = {av.x, av.y, av.z, av.w};
            float b[8] = {b0.x, b0.y, b0.z, b0.w, b1.x, b1.y, b1.z, b1.w};
            #pragma unroll
            for (int i = 0; i < 4; i++)
                #pragma unroll
                for (int j = 0; j < 8; j++) acc[i][j] += a[i] * b[j];
        }
        cur ^= 1;
        __syncthreads();
    }
    #pragma unroll
    for (int i = 0; i < 4; i++)
        #pragma unroll
        for (int j = 0; j < 4; j++) {
            atomicAdd(&g_G[(r0 + i) * D + cA + j], acc[i][j]);
            atomicAdd(&g_G[(r0 + i) * D + cB + j], acc[i][j + 4]);
        }
}

// ---------------------------------------------------------------- E1' = 0.5*x@W1 + b1  (off critical path)
__global__ __launch_bounds__(512, 1) void k_E1(const float* __restrict__ x,
                        const float* __restrict__ w1, const float* __restrict__ b1,
                        int N, int nChunks) {
    extern __shared__ float sm[];
    float* bufs[2] = { sm, sm + 128 * PAD };
    float* w1s = sm + 2 * 128 * PAD;
    __shared__ float be1_s[D];
    int tid = threadIdx.x;
    int ty = tid >> 4, tx = tid & 15;
    int r0 = ty * 4, cA = tx * 4, cB = cA + 64;
    int stride = gridDim.x;

    for (int idx = tid; idx < D * 32; idx += 512) {
        int r = idx >> 5, c4 = idx & 31;
        *(float4*)&w1s[r * PAD + c4 * 4] = ((const float4*)w1)[idx];
    }
    if (tid < D) be1_s[tid] = b1[tid];

    int ch = blockIdx.x;
    if (ch < nChunks) {
        int R0 = ch * 128;
        if (R0 + 128 <= N) {
            #pragma unroll
            for (int u = 0; u < 8; u++) {
                int idx = tid + u * 512;
                int r = idx >> 5, c4 = idx & 31;
                cp16(smem_u32(&bufs[0][r * PAD + c4 * 4]), &x[((size_t)(R0 + r)) * 128 + c4 * 4]);
            }
        } else {
            #pragma unroll
            for (int u = 0; u < 8; u++) {
                int idx = tid + u * 512;
                int r = idx >> 5, c4 = idx & 31;
                int gr = R0 + r;
                float4 v = (gr < N) ? ((const float4*)x)[(size_t)gr * 32 + c4]
                                    : make_float4(0.f, 0.f, 0.f, 0.f);
                *(float4*)&bufs[0][r * PAD + c4 * 4] = v;
            }
        }
        CP_COMMIT();
    }

    int cur = 0;
    for (; ch < nChunks; ch += stride) {
        int R0 = ch * 128;
        int nxt = ch + stride;
        if (nxt < nChunks) {
            float* bn = bufs[cur ^ 1];
            int R1 = nxt * 128;
            if (R1 + 128 <= N) {
                #pragma unroll
                for (int u = 0; u < 8; u++) {
                    int idx = tid + u * 512;
                    int r = idx >> 5, c4 = idx & 31;
                    cp16(smem_u32(&bn[r * PAD + c4 * 4]), &x[((size_t)(R1 + r)) * 128 + c4 * 4]);
                }
            } else {
                #pragma unroll
                for (int u = 0; u < 8; u++) {
                    int idx = tid + u * 512;
                    int r = idx >> 5, c4 = idx & 31;
                    int gr = R1 + r;
                    float4 v = (gr < N) ? ((const float4*)x)[(size_t)gr * 32 + c4]
                                        : make_float4(0.f, 0.f, 0.f, 0.f);
                    *(float4*)&bn[r * PAD + c4 * 4] = v;
                }
            }
            CP_COMMIT();
            CP_WAIT(1);
        } else {
            CP_WAIT(0);
        }
        __syncthreads();
        const float* bc = bufs[cur];

        float acc[4][8];
        #pragma unroll
        for (int i = 0; i < 4; i++)
            #pragma unroll
            for (int j = 0; j < 8; j++) acc[i][j] = 0.0f;
        #pragma unroll 4
        for (int k = 0; k < 128; k++) {
            float a[4];
            #pragma unroll
            for (int i = 0; i < 4; i++) a[i] = bc[(r0 + i) * PAD + k];
            float4 b0 = *(const float4*)&w1s[k * PAD + cA];
            float4 b1v = *(const float4*)&w1s[k * PAD + cB];
            float b[8] = {b0.x, b0.y, b0.z, b0.w, b1v.x, b1v.y, b1v.z, b1v.w};
            #pragma unroll
            for (int i = 0; i < 4; i++)
                #pragma unroll
                for (int j = 0; j < 8; j++) acc[i][j] += a[i] * b[j];
        }
        #pragma unroll
        for (int i = 0; i < 4; i++) {
            int gr = R0 + r0 + i;
            if (gr >= N) continue;
            float o[8];
            #pragma unroll
            for (int j = 0; j < 8; j++) {
                int col = (j < 4) ? (cA + j) : (cB + j - 4);
                o[j] = 0.5f * acc[i][j] + be1_s[col];
            }
            *(float4*)&g_E1[(size_t)gr * 128 + cA] = *(float4*)&o[0];
            *(float4*)&g_E1[(size_t)gr * 128 + cB] = *(float4*)&o[4];
        }
        cur ^= 1;
        __syncthreads();
    }
}

// ---------------------------------------------------------------- matrix squaring
__global__ void k_sq(int it) {
    extern __shared__ float As[];   // 128*128
    const float* in = (it == 0) ? g_G : ((it & 1) ? g_Ea : g_Eb);
    float* outp = (it & 1) ? g_Eb : g_Ea;
    int tid = threadIdx.x;
    __shared__ float redm[8];

    if (it == 0) {
        float m = 0.0f;
        for (int idx = tid; idx < D * D / 4; idx += 256) {
            float4 v = ((const float4*)in)[idx];
            ((float4*)As)[idx] = v;
            m = fmaxf(m, fmaxf(fmaxf(fabsf(v.x), fabsf(v.y)), fmaxf(fabsf(v.z), fabsf(v.w))));
        }
        #pragma unroll
        for (int o = 16; o; o >>= 1) m = fmaxf(m, __shfl_xor_sync(0xffffffffu, m, o));
        if ((tid & 31) == 0) redm[tid >> 5] = m;
        __syncthreads();
        if (tid < 32) {
            float mm = (tid < 8) ? redm[tid] : 0.0f;
            #pragma unroll
            for (int o = 4; o; o >>= 1) mm = fmaxf(mm, __shfl_xor_sync(0xffffffffu, mm, o));
            if (tid == 0) redm[0] = mm;
        }
        __syncthreads();
        float inv = 1.0f / redm[0];
        for (int idx = tid; idx < D * D / 4; idx += 256) {
            float4 v = ((float4*)As)[idx];
            v.x *= inv; v.y *= inv; v.z *= inv; v.w *= inv;
            ((float4*)As)[idx] = v;
        }
    } else {
        float inv = 1.0f / g_scale[it];
        for (int idx = tid; idx < D * D / 4; idx += 256) {
            float4 v = ((const float4*)in)[idx];
            v.x *= inv; v.y *= inv; v.z *= inv; v.w *= inv;
            ((float4*)As)[idx] = v;
        }
    }
    __syncthreads();

    int ty = tid >> 5, tx = tid & 31;
    int r0 = blockIdx.x * 16 + ty * 2, c0 = tx * 4;
    float acc0[4] = {0.f, 0.f, 0.f, 0.f};
    float acc1[4] = {0.f, 0.f, 0.f, 0.f};
    #pragma unroll 4
    for (int k = 0; k < D; k++) {
        float a0 = As[r0 * D + k];
        float a1v = As[(r0 + 1) * D + k];
        float4 b = *(const float4*)&As[k * D + c0];
        acc0[0] += a0 * b.x; acc0[1] += a0 * b.y; acc0[2] += a0 * b.z; acc0[3] += a0 * b.w;
        acc1[0] += a1v * b.x; acc1[1] += a1v * b.y; acc1[2] += a1v * b.z; acc1[3] += a1v * b.w;
    }
    *(float4*)&outp[r0 * D + c0] = *(float4*)&acc0[0];
    *(float4*)&outp[(r0 + 1) * D + c0] = *(float4*)&acc1[0];
    float m = 0.0f;
    #pragma unroll
    for (int j = 0; j < 4; j++) m = fmaxf(m, fmaxf(fabsf(acc0[j]), fabsf(acc1[j])));
    #pragma unroll
    for (int o = 16; o; o >>= 1) m = fmaxf(m, __shfl_xor_sync(0xffffffffu, m, o));
    if (tx == 0) atomicMax((int*)&g_scale[it + 1], __float_as_int(m));
}

// ---------------------------------------------------------------- v1 extraction + a1
__global__ void k_extract(const float* __restrict__ w1) {
    extern __shared__ float sm[];
    float* As = sm;                  // 128*PADE
    float* vv = sm + D * PADE;
    float* uu = vv + D;
    float* red = uu + D;
    __shared__ int redi[128];
    __shared__ int jm;
    int t = threadIdx.x;             // 128 threads

    for (int idx = t; idx < D * D; idx += 128) {
        int r = idx >> 7, c = idx & 127;
        As[r * PADE + c] = g_Eb[idx];
    }
    __syncthreads();
    red[t] = As[t * PADE + t]; redi[t] = t;
    __syncthreads();
    for (int s = 64; s > 0; s >>= 1) {
        if (t < s && red[t + s] > red[t]) { red[t] = red[t + s]; redi[t] = redi[t + s]; }
        __syncthreads();
    }
    if (t == 0) jm = redi[0];
    __syncthreads();
    vv[t] = As[jm * PADE + t];
    __syncthreads();

    for (int itr = 0; itr < NREF; itr++) {
        float s = 0.0f;
        #pragma unroll 8
        for (int c = 0; c < D; c++) s += As[t * PADE + c] * vv[c];
        uu[t] = s;
        red[t] = s * s;
        __syncthreads();
        for (int r2 = 64; r2 > 0; r2 >>= 1) {
            if (t < r2) red[t] += red[t + r2];
            __syncthreads();
        }
        float inv = rsqrtf(fmaxf(red[0], 1e-30f));
        __syncthreads();
        vv[t] = uu[t] * inv;
        __syncthreads();
    }

    g_v1[t] = vv[t];
    float a = 0.0f;
    #pragma unroll 8
    for (int d2 = 0; d2 < D; d2++) a += vv[d2] * w1[d2 * D + t];
    g_a1[t] = a;
}

// ---------------------------------------------------------------- q = x @ v1 (warp per row)
__global__ void k_q(const float* __restrict__ x, int N) {
    int w = (blockIdx.x * blockDim.x + threadIdx.x) >> 5;
    int lane = threadIdx.x & 31;
    if (w >= N) return;
    float4 xv = ((const float4*)x)[(size_t)w * 32 + lane];
    float4 vv = *(const float4*)&g_v1[lane * 4];
    float s = xv.x * vv.x + xv.y * vv.y + xv.z * vv.z + xv.w * vv.w;
    #pragma unroll
    for (int o = 16; o; o >>= 1) s += __shfl_xor_sync(0xffffffffu, s, o);
    if (lane == 0) g_q[w] = s;
}

// ---------------------------------------------------------------- final: relu(E1' + 0.5 q a1^T) @ W2 epilogue
// out = (relu(z) @ W2 + b2)*scores + 0.5 x + 0.5 q v1^T
__global__ __launch_bounds__(512, 1) void k_final2(const float* __restrict__ x,
                        const float* __restrict__ b2, const float* __restrict__ w2,
                        float* __restrict__ out, int N, int nChunks) {
    extern __shared__ float sm[];
    float* bufs[2] = { sm, sm + 128 * PAD };     // E1 chunk -> relu(z) in place
    float* w2s = sm + 2 * 128 * PAD;
    float* q_s = w2s + 128 * PAD;                // 128
    float* sc_s = q_s + 128;                     // 128
    __shared__ float v1_s[D], a1_s[D], be2_s[D];

    int tid = threadIdx.x;
    int ty = tid >> 4, tx = tid & 15;
    int r0 = ty * 4, cA = tx * 4, cB = cA + 64;
    int stride = gridDim.x;

    for (int idx = tid; idx < D * 32; idx += 512) {
        int r = idx >> 5, c4 = idx & 31;
        *(float4*)&w2s[r * PAD + c4 * 4] = ((const float4*)w2)[idx];
    }
    if (tid < D) {
        v1_s[tid] = g_v1[tid]; a1_s[tid] = g_a1[tid]; be2_s[tid] = b2[tid];
    }

    int ch = blockIdx.x;
    if (ch < nChunks) {
        int R0 = ch * 128;              // g_E1 capacity covers all chunk rows
        #pragma unroll
        for (int u = 0; u < 8; u++) {
            int idx = tid + u * 512;
            int r = idx >> 5, c4 = idx & 31;
            cp16(smem_u32(&bufs[0][r * PAD + c4 * 4]), &g_E1[((size_t)(R0 + r)) * 128 + c4 * 4]);
        }
        CP_COMMIT();
    }

    int cur = 0;
    for (; ch < nChunks; ch += stride) {
        int R0 = ch * 128;
        int nxt = ch + stride;
        if (nxt < nChunks) {
            float* bn = bufs[cur ^ 1];
            int R1 = nxt * 128;
            #pragma unroll
            for (int u = 0; u < 8; u++) {
                int idx = tid + u * 512;
                int r = idx >> 5, c4 = idx & 31;
                cp16(smem_u32(&bn[r * PAD + c4 * 4]), &g_E1[((size_t)(R1 + r)) * 128 + c4 * 4]);
            }
            CP_COMMIT();
            CP_WAIT(1);
        } else {
            CP_WAIT(0);
        }
        if (tid < 128) {
            int gr = R0 + tid;
            q_s[tid]  = (gr < N) ? g_q[gr] : 0.0f;
            sc_s[tid] = (gr < N) ? g_scores[gr] : 0.0f;
        }
        __syncthreads();
        float* bc = bufs[cur];

        // in-place: z = E1' + 0.5 q a1^T ; relu
        #pragma unroll
        for (int i = 0; i < 4; i++) {
            float hq = 0.5f * q_s[r0 + i];
            float4 e0 = *(const float4*)&bc[(r0 + i) * PAD + cA];
            float4 e1 = *(const float4*)&bc[(r0 + i) * PAD + cB];
            float e[8] = {e0.x, e0.y, e0.z, e0.w, e1.x, e1.y, e1.z, e1.w};
            float o[8];
            #pragma unroll
            for (int j = 0; j < 8; j++) {
                int col = (j < 4) ? (cA + j) : (cB + j - 4);
                float z = e[j] + hq * a1_s[col];
                o[j] = z > 0.0f ? z : 0.0f;
            }
            *(float4*)&bc[(r0 + i) * PAD + cA] = *(float4*)&o[0];
            *(float4*)&bc[(r0 + i) * PAD + cB] = *(float4*)&o[4];
        }
        __syncthreads();

        // GEMM2: enh = relu(z) @ W2
        float acc[4][8];
        #pragma unroll
        for (int i = 0; i < 4; i++)
            #pragma unroll
            for (int j = 0; j < 8; j++) acc[i][j] = 0.0f;
        #pragma unroll 4
        for (int k = 0; k < 128; k++) {
            float a[4];
            #pragma unroll
            for (int i = 0; i < 4; i++) a[i] = bc[(r0 + i) * PAD + k];
            float4 b0 = *(const float4*)&w2s[k * PAD + cA];
            float4 b1v = *(const float4*)&w2s[k * PAD + cB];
            float b[8] = {b0.x, b0.y, b0.z, b0.w, b1v.x, b1v.y, b1v.z, b1v.w};
            #pragma unroll
            for (int i = 0; i < 4; i++)
                #pragma unroll
                for (int j = 0; j < 8; j++) acc[i][j] += a[i] * b[j];
        }
        // epilogue: residual (x from gmem/L2) + write
        #pragma unroll
        for (int i = 0; i < 4; i++) {
            int gr = R0 + r0 + i;
            if (gr >= N) continue;
            float sc = sc_s[r0 + i], q = q_s[r0 + i];
            float4 xa = ((const float4*)x)[(size_t)gr * 32 + (cA >> 2)];
            float4 xb = ((const float4*)x)[(size_t)gr * 32 + (cB >> 2)];
            float xv[8] = {xa.x, xa.y, xa.z, xa.w, xb.x, xb.y, xb.z, xb.w};
            float o[8];
            #pragma unroll
            for (int j = 0; j < 8; j++) {
                int col = (j < 4) ? (cA + j) : (cB + j - 4);
                o[j] = (acc[i][j] + be2_s[col]) * sc
                     + 0.5f * xv[j] + 0.5f * q * v1_s[col];
            }
            ((float4*)out)[(size_t)gr * 32 + (cA >> 2)] = *(float4*)&o[0];
            ((float4*)out)[(size_t)gr * 32 + (cB >> 2)] = *(float4*)&o[4];
        }
        cur ^= 1;
        __syncthreads();
    }
}

// ---------------------------------------------------------------- launch
extern "C" void kernel_launch(void* const* d_in, const int* in_sizes, int n_in,
                              void* d_out, int out_size) {
    const float* x       = (const float*)d_in[0];
    const void*  ei      = d_in[1];
    const float* ew      = (const float*)d_in[2];
    const float* w_gcn   = (const float*)d_in[3];
    const float* b_gcn   = (const float*)d_in[4];
    const float* w_score = (const float*)d_in[5];
    const float* b_score = (const float*)d_in[6];
    const float* alpha   = (const float*)d_in[7];
    const float* beta    = (const float*)d_in[8];
    const float* w_e1    = (const float*)d_in[9];
    const float* b_e1    = (const float*)d_in[10];
    const float* w_e2    = (const float*)d_in[11];
    const float* b_e2    = (const float*)d_in[12];
    float* out = (float*)d_out;

    int N = in_sizes[0] / D;
    int E = in_sizes[2];
    int nChunks = (N + 127) / 128;
    int NB = (N + 255) / 256;
    int EB = (E + 255) / 256;
    int ZB = ((N > D * D ? N : D * D) + 255) / 256;
    int PB = (N * 32 + 255) / 256;

    const int SMG  = 2 * 128 * PAD * 4;
    const int SME1 = 3 * 128 * PAD * 4;
    const int SMF  = (3 * 128 * PAD + 256) * 4;
    const int SMS  = D * D * 4;
    const int SMX  = (D * PADE + 3 * 128) * 4;

    static int init_done = 0;
    static cudaStream_t s1, s2;
    static cudaEvent_t evFork, evJoin, evG, evE1;
    if (!init_done) {
        cudaFuncSetAttribute(k_G,       cudaFuncAttributeMaxDynamicSharedMemorySize, SMG);
        cudaFuncSetAttribute(k_E1,      cudaFuncAttributeMaxDynamicSharedMemorySize, SME1);
        cudaFuncSetAttribute(k_sq,      cudaFuncAttributeMaxDynamicSharedMemorySize, SMS);
        cudaFuncSetAttribute(k_extract, cudaFuncAttributeMaxDynamicSharedMemorySize, SMX);
        cudaFuncSetAttribute(k_final2,  cudaFuncAttributeMaxDynamicSharedMemorySize, SMF);
        cudaStreamCreateWithFlags(&s1, cudaStreamNonBlocking);
        cudaStreamCreateWithFlags(&s2, cudaStreamNonBlocking);
        cudaEventCreateWithFlags(&evFork, cudaEventDisableTiming);
        cudaEventCreateWithFlags(&evJoin, cudaEventDisableTiming);
        cudaEventCreateWithFlags(&evG,    cudaEventDisableTiming);
        cudaEventCreateWithFlags(&evE1,   cudaEventDisableTiming);
        init_done = 1;
    }

    k_pre<<<ZB + 2, 256>>>((const long long*)ei, E, N, w_gcn, b_gcn, w_score, b_score, ZB);

    cudaEventRecord(evFork, 0);
    cudaStreamWaitEvent(s1, evFork, 0);
    cudaStreamWaitEvent(s2, evFork, 0);

    // edge/score chain (s1) — hidden under the FMA-bound work on s0/s2
    k_deg<<<EB, 256, 0, s1>>>(ei, E);
    k_p<<<PB, 256, 0, s1>>>(x, N);
    k_dinv<<<NB, 256, 0, s1>>>(N);
    k_edge<<<EB, 256, 0, s1>>>(ei, E);
    k_scores<<<NB, 256, 0, s1>>>(N);
    k_gate<<<EB, 256, 0, s1>>>(ei, ew, alpha, beta, out + (size_t)N * D, E);
    cudaEventRecord(evJoin, s1);

    // s0: Gram -> squaring chain -> extract -> q
    k_G<<<148, 512, SMG>>>(x, N, nChunks);
    cudaEventRecord(evG, 0);
    for (int it = 0; it < NSQ; it++)
        k_sq<<<8, 256, SMS>>>(it);
    k_extract<<<1, 128, SMX>>>(w_e1);
    k_q<<<PB, 256>>>(x, N);

    // s2: E1' GEMM, concurrent with the squaring chain (which uses only 8 SMs)
    cudaStreamWaitEvent(s2, evG, 0);
    k_E1<<<148, 512, SME1, s2>>>(x, w_e1, b_e1, N, nChunks);
    cudaEventRecord(evE1, s2);

    cudaStreamWaitEvent(0, evJoin, 0);
    cudaStreamWaitEvent(0, evE1, 0);
    k_final2<<<148, 512, SMF>>>(x, b_e2, w_e2, out, N, nChunks);
}

// round 5
// speedup vs baseline: 1.2082x; 1.2082x over previous
#include <cuda_runtime.h>
#include <math.h>
#include <stdint.h>

#define D 128
#define PAD 132            // smem row pitch (floats)
#define PADE 129
#define NMAX 65536
#define NSQ 10
#define NREF 5

static __device__ int   g_degi[NMAX];
static __device__ float g_dinv[NMAX];
static __device__ float g_p[NMAX];
static __device__ float g_sacc[NMAX];
static __device__ float g_scores[NMAX];
static __device__ __align__(16) float g_G[D * D];
static __device__ __align__(16) float g_Ea[D * D];
static __device__ __align__(16) float g_Eb[D * D];
static __device__ float g_scale[16];
static __device__ float g_v1[D];
static __device__ float g_a1[D];
static __device__ float g_wv[D];
static __device__ float g_bg;
static __device__ int   g_i32;

// ---------------------------------------------------------------- utilities
__device__ __forceinline__ void load_edge(const void* ei, int E, int e, int& s, int& t) {
    if (g_i32) {
        const int* p = (const int*)ei;
        s = p[e]; t = p[E + e];
    } else {
        const long long* p = (const long long*)ei;
        s = (int)p[e]; t = (int)p[E + e];
    }
}

__device__ __forceinline__ float sigmoidf_(float z) {
    return 1.0f / (1.0f + expf(-z));
}

__device__ __forceinline__ unsigned smem_u32(const void* p) {
    return (unsigned)__cvta_generic_to_shared(p);
}
__device__ __forceinline__ void cp16(unsigned s, const void* g) {
    asm volatile("cp.async.cg.shared.global [%0], [%1], 16;\n" :: "r"(s), "l"(g));
}
#define CP_COMMIT() asm volatile("cp.async.commit_group;\n" ::)
#define CP_WAIT(n)  asm volatile("cp.async.wait_group %0;\n" :: "n"(n))

__device__ __forceinline__ uint32_t tf32cvt(float f) {
    uint32_t u;
    asm("cvt.rna.tf32.f32 %0, %1;" : "=r"(u) : "f"(f));
    return u;
}

__device__ __forceinline__ void mma_tf32(float* c, uint32_t a0, uint32_t a1, uint32_t a2, uint32_t a3,
                                         uint32_t b0, uint32_t b1) {
    asm volatile("mma.sync.aligned.m16n8k8.row.col.f32.tf32.tf32.f32 "
                 "{%0,%1,%2,%3}, {%4,%5,%6,%7}, {%8,%9}, {%0,%1,%2,%3};"
                 : "+f"(c[0]), "+f"(c[1]), "+f"(c[2]), "+f"(c[3])
                 : "r"(a0), "r"(a1), "r"(a2), "r"(a3), "r"(b0), "r"(b1));
}

// ---------------------------------------------------------------- fused prologue
__global__ void k_pre(const long long* ei, int E, int N,
                      const float* __restrict__ wg, const float* __restrict__ bgc,
                      const float* __restrict__ ws, const float* __restrict__ bs, int ZB) {
    int b = blockIdx.x, t = threadIdx.x;
    if (b < ZB) {
        int i = b * 256 + t;
        if (i < N) g_degi[i] = 0;
        if (i < D * D) g_G[i] = 0.0f;
        if (i < 16) g_scale[i] = 0.0f;
    } else if (b == ZB) {
        __shared__ int flag;
        if (t == 0) flag = 0;
        __syncthreads();
        int n = E < 1024 ? E : 1024;
        for (int e = t; e < n; e += 256)
            if ((unsigned long long)ei[e] >= (unsigned long long)N) flag = 1;
        __syncthreads();
        if (t == 0) g_i32 = flag;
    } else {
        __shared__ float wss[D];
        if (t < D) wss[t] = ws[t];
        __syncthreads();
        if (t < D) {
            float s = 0.0f;
            #pragma unroll 8
            for (int m = 0; m < D; m++) s += wg[t * D + m] * wss[m];
            g_wv[t] = s;
        }
        if (t == 0) {
            float bsum = bs[0];
            for (int m = 0; m < D; m++) bsum += bgc[m] * wss[m];
            g_bg = bsum;
        }
    }
}

// ---------------------------------------------------------------- edge/score chain (s1)
__global__ void k_p(const float* __restrict__ x, int N) {
    int w = (blockIdx.x * blockDim.x + threadIdx.x) >> 5;
    int lane = threadIdx.x & 31;
    if (w >= N) return;
    float4 xv = ((const float4*)x)[(size_t)w * 32 + lane];
    float4 wv = *(const float4*)&g_wv[lane * 4];
    float s = xv.x * wv.x + xv.y * wv.y + xv.z * wv.z + xv.w * wv.w;
    #pragma unroll
    for (int o = 16; o; o >>= 1) s += __shfl_xor_sync(0xffffffffu, s, o);
    if (lane == 0) g_p[w] = s;
}

__global__ void k_deg(const void* ei, int E) {
    int e = blockIdx.x * 256 + threadIdx.x;
    if (e >= E) return;
    int t = g_i32 ? ((const int*)ei)[E + e] : (int)((const long long*)ei)[E + e];
    atomicAdd(&g_degi[t], 1);
}

__global__ void k_dinv(int N) {
    int i = blockIdx.x * 256 + threadIdx.x;
    if (i >= N) return;
    float di = rsqrtf((float)(g_degi[i] + 1));
    g_dinv[i] = di;
    g_sacc[i] = di * di * g_p[i];
}

__global__ void k_edge(const void* ei, int E) {
    int e = blockIdx.x * 256 + threadIdx.x;
    if (e >= E) return;
    int s, t; load_edge(ei, E, e, s, t);
    atomicAdd(&g_sacc[t], g_dinv[s] * g_dinv[t] * g_p[s]);
}

__global__ void k_scores(int N) {
    int i = blockIdx.x * 256 + threadIdx.x;
    if (i >= N) return;
    g_scores[i] = sigmoidf_(g_sacc[i] + g_bg);
}

__global__ void k_gate(const void* ei, const float* __restrict__ ew,
                       const float* __restrict__ al, const float* __restrict__ be,
                       float* __restrict__ out, int E) {
    int e = blockIdx.x * 256 + threadIdx.x;
    if (e >= E) return;
    int s, t; load_edge(ei, E, e, s, t);
    float z = al[0] * (g_scores[s] + g_scores[t]) + be[0];
    out[e] = ew[e] * sigmoidf_(z);
}

// ---------------------------------------------------------------- Gram, cp.async double-buffered (fp32)
__global__ __launch_bounds__(512, 1) void k_G(const float* __restrict__ x, int N, int nChunks) {
    extern __shared__ float sm[];
    float* bufs[2] = { sm, sm + 128 * PAD };
    int tid = threadIdx.x;
    int ty = tid >> 4, tx = tid & 15;
    int r0 = ty * 4, cA = tx * 4, cB = cA + 64;
    int stride = gridDim.x;

    float acc[4][8];
    #pragma unroll
    for (int i = 0; i < 4; i++)
        #pragma unroll
        for (int j = 0; j < 8; j++) acc[i][j] = 0.0f;

    int ch = blockIdx.x;
    if (ch < nChunks) {
        int R0 = ch * 128;
        if (R0 + 128 <= N) {
            #pragma unroll
            for (int u = 0; u < 8; u++) {
                int idx = tid + u * 512;
                int r = idx >> 5, c4 = idx & 31;
                cp16(smem_u32(&bufs[0][r * PAD + c4 * 4]), &x[((size_t)(R0 + r)) * 128 + c4 * 4]);
            }
        } else {
            #pragma unroll
            for (int u = 0; u < 8; u++) {
                int idx = tid + u * 512;
                int r = idx >> 5, c4 = idx & 31;
                int gr = R0 + r;
                float4 v = (gr < N) ? ((const float4*)x)[(size_t)gr * 32 + c4]
                                    : make_float4(0.f, 0.f, 0.f, 0.f);
                *(float4*)&bufs[0][r * PAD + c4 * 4] = v;
            }
        }
        CP_COMMIT();
    }

    int cur = 0;
    for (; ch < nChunks; ch += stride) {
        int nxt = ch + stride;
        if (nxt < nChunks) {
            float* bn = bufs[cur ^ 1];
            int R0 = nxt * 128;
            if (R0 + 128 <= N) {
                #pragma unroll
                for (int u = 0; u < 8; u++) {
                    int idx = tid + u * 512;
                    int r = idx >> 5, c4 = idx & 31;
                    cp16(smem_u32(&bn[r * PAD + c4 * 4]), &x[((size_t)(R0 + r)) * 128 + c4 * 4]);
                }
            } else {
                #pragma unroll
                for (int u = 0; u < 8; u++) {
                    int idx = tid + u * 512;
                    int r = idx >> 5, c4 = idx & 31;
                    int gr = R0 + r;
                    float4 v = (gr < N) ? ((const float4*)x)[(size_t)gr * 32 + c4]
                                        : make_float4(0.f, 0.f, 0.f, 0.f);
                    *(float4*)&bn[r * PAD + c4 * 4] = v;
                }
            }
            CP_COMMIT();
            CP_WAIT(1);
        } else {
            CP_WAIT(0);
        }
        __syncthreads();
        const float* bc = bufs[cur];
        #pragma unroll 4
        for (int k = 0; k < 128; k++) {
            float4 av = *(const float4*)&bc[k * PAD + r0];
            float4 b0 = *(const float4*)&bc[k * PAD + cA];
            float4 b1 = *(const float4*)&bc[k * PAD + cB];
            float a[4] = {av.x, av.y, av.z, av.w};
            float b[8] = {b0.x, b0.y, b0.z, b0.w, b1.x, b1.y, b1.z, b1.w};
            #pragma unroll
            for (int i = 0; i < 4; i++)
                #pragma unroll
                for (int j = 0; j < 8; j++) acc[i][j] += a[i] * b[j];
        }
        cur ^= 1;
        __syncthreads();
    }
    #pragma unroll
    for (int i = 0; i < 4; i++)
        #pragma unroll
        for (int j = 0; j < 4; j++) {
            atomicAdd(&g_G[(r0 + i) * D + cA + j], acc[i][j]);
            atomicAdd(&g_G[(r0 + i) * D + cB + j], acc[i][j + 4]);
        }
}

// ---------------------------------------------------------------- matrix squaring
__global__ void k_sq(int it) {
    extern __shared__ float As[];
    const float* in = (it == 0) ? g_G : ((it & 1) ? g_Ea : g_Eb);
    float* outp = (it & 1) ? g_Eb : g_Ea;
    int tid = threadIdx.x;
    __shared__ float redm[8];

    if (it == 0) {
        float m = 0.0f;
        for (int idx = tid; idx < D * D / 4; idx += 256) {
            float4 v = ((const float4*)in)[idx];
            ((float4*)As)[idx] = v;
            m = fmaxf(m, fmaxf(fmaxf(fabsf(v.x), fabsf(v.y)), fmaxf(fabsf(v.z), fabsf(v.w))));
        }
        #pragma unroll
        for (int o = 16; o; o >>= 1) m = fmaxf(m, __shfl_xor_sync(0xffffffffu, m, o));
        if ((tid & 31) == 0) redm[tid >> 5] = m;
        __syncthreads();
        if (tid < 32) {
            float mm = (tid < 8) ? redm[tid] : 0.0f;
            #pragma unroll
            for (int o = 4; o; o >>= 1) mm = fmaxf(mm, __shfl_xor_sync(0xffffffffu, mm, o));
            if (tid == 0) redm[0] = mm;
        }
        __syncthreads();
        float inv = 1.0f / redm[0];
        for (int idx = tid; idx < D * D / 4; idx += 256) {
            float4 v = ((float4*)As)[idx];
            v.x *= inv; v.y *= inv; v.z *= inv; v.w *= inv;
            ((float4*)As)[idx] = v;
        }
    } else {
        float inv = 1.0f / g_scale[it];
        for (int idx = tid; idx < D * D / 4; idx += 256) {
            float4 v = ((const float4*)in)[idx];
            v.x *= inv; v.y *= inv; v.z *= inv; v.w *= inv;
            ((float4*)As)[idx] = v;
        }
    }
    __syncthreads();

    int ty = tid >> 5, tx = tid & 31;
    int r0 = blockIdx.x * 16 + ty * 2, c0 = tx * 4;
    float acc0[4] = {0.f, 0.f, 0.f, 0.f};
    float acc1[4] = {0.f, 0.f, 0.f, 0.f};
    #pragma unroll 4
    for (int k = 0; k < D; k++) {
        float a0 = As[r0 * D + k];
        float a1v = As[(r0 + 1) * D + k];
        float4 b = *(const float4*)&As[k * D + c0];
        acc0[0] += a0 * b.x; acc0[1] += a0 * b.y; acc0[2] += a0 * b.z; acc0[3] += a0 * b.w;
        acc1[0] += a1v * b.x; acc1[1] += a1v * b.y; acc1[2] += a1v * b.z; acc1[3] += a1v * b.w;
    }
    *(float4*)&outp[r0 * D + c0] = *(float4*)&acc0[0];
    *(float4*)&outp[(r0 + 1) * D + c0] = *(float4*)&acc1[0];
    float m = 0.0f;
    #pragma unroll
    for (int j = 0; j < 4; j++) m = fmaxf(m, fmaxf(fabsf(acc0[j]), fabsf(acc1[j])));
    #pragma unroll
    for (int o = 16; o; o >>= 1) m = fmaxf(m, __shfl_xor_sync(0xffffffffu, m, o));
    if (tx == 0) atomicMax((int*)&g_scale[it + 1], __float_as_int(m));
}

// ---------------------------------------------------------------- v1 extraction + a1
__global__ void k_extract(const float* __restrict__ w1) {
    extern __shared__ float sm[];
    float* As = sm;
    float* vv = sm + D * PADE;
    float* uu = vv + D;
    float* red = uu + D;
    __shared__ int redi[128];
    __shared__ int jm;
    int t = threadIdx.x;

    for (int idx = t; idx < D * D; idx += 128) {
        int r = idx >> 7, c = idx & 127;
        As[r * PADE + c] = g_Eb[idx];
    }
    __syncthreads();
    red[t] = As[t * PADE + t]; redi[t] = t;
    __syncthreads();
    for (int s = 64; s > 0; s >>= 1) {
        if (t < s && red[t + s] > red[t]) { red[t] = red[t + s]; redi[t] = redi[t + s]; }
        __syncthreads();
    }
    if (t == 0) jm = redi[0];
    __syncthreads();
    vv[t] = As[jm * PADE + t];
    __syncthreads();

    for (int itr = 0; itr < NREF; itr++) {
        float s = 0.0f;
        #pragma unroll 8
        for (int c = 0; c < D; c++) s += As[t * PADE + c] * vv[c];
        uu[t] = s;
        red[t] = s * s;
        __syncthreads();
        for (int r2 = 64; r2 > 0; r2 >>= 1) {
            if (t < r2) red[t] += red[t + r2];
            __syncthreads();
        }
        float inv = rsqrtf(fmaxf(red[0], 1e-30f));
        __syncthreads();
        vv[t] = uu[t] * inv;
        __syncthreads();
    }

    g_v1[t] = vv[t];
    float a = 0.0f;
    #pragma unroll 8
    for (int d2 = 0; d2 < D; d2++) a += vv[d2] * w1[d2 * D + t];
    g_a1[t] = a;
}

// ---------------------------------------------------------------- fused enhancer, tf32 tensor-core core
// out = (relu(0.5 x@W1 + 0.5 q a1^T + b1) @ W2 + b2)*scores + 0.5 x + 0.5 q v1^T
// A-side 2-pass hi/lo split (error ~1e-4); weights tf32-rounded once, stored TRANSPOSED [n][k].
__global__ __launch_bounds__(512, 1) void k_final3(const float* __restrict__ x,
                        const float* __restrict__ b1, const float* __restrict__ b2,
                        const float* __restrict__ w1, const float* __restrict__ w2,
                        float* __restrict__ out, int N, int nChunks) {
    extern __shared__ float sm[];
    float* xs  = sm;                       // x chunk -> relu(z), 128*PAD
    float* w1t = sm + 128 * PAD;           // W1^T tf32, [n][k]
    float* w2t = w1t + 128 * PAD;
    float* q_s = w2t + 128 * PAD;          // 128
    float* sc_s = q_s + 128;               // 128
    __shared__ float v1_s[D], a1_s[D], be1_s[D], be2_s[D];

    int tid = threadIdx.x;
    int wid = tid >> 5, lane = tid & 31;
    int wm = wid >> 2, wn = wid & 3;       // 4x4 warp grid, 32x32 warp tile
    int gid = lane >> 2, tg = lane & 3;
    int stride = gridDim.x;

    // load weights: transpose + tf32-round
    for (int idx = tid; idx < D * D; idx += 512) {
        int k = idx >> 7, n = idx & 127;
        w1t[n * PAD + k] = __uint_as_float(tf32cvt(w1[idx]));
        w2t[n * PAD + k] = __uint_as_float(tf32cvt(w2[idx]));
    }
    if (tid < D) {
        v1_s[tid] = g_v1[tid]; a1_s[tid] = g_a1[tid];
        be1_s[tid] = b1[tid];  be2_s[tid] = b2[tid];
    }

    float4 pf[8];
    int ch = blockIdx.x;
    if (ch < nChunks) {
        int R0 = ch * 128;
        #pragma unroll
        for (int u = 0; u < 8; u++) {
            int idx = tid + u * 512;
            int r = idx >> 5, c4 = idx & 31;
            int gr = R0 + r;
            pf[u] = (gr < N) ? ((const float4*)x)[(size_t)gr * 32 + c4]
                             : make_float4(0.f, 0.f, 0.f, 0.f);
        }
    }

    for (; ch < nChunks; ch += stride) {
        int R0 = ch * 128;
        __syncthreads();                  // xs free of previous-iteration reads
        #pragma unroll
        for (int u = 0; u < 8; u++) {
            int idx = tid + u * 512;
            int r = idx >> 5, c4 = idx & 31;
            *(float4*)&xs[r * PAD + c4 * 4] = pf[u];
        }
        if (tid < 128) sc_s[tid] = (R0 + tid < N) ? g_scores[R0 + tid] : 0.0f;
        __syncthreads();
        if (tid < 128) {
            float q = 0.0f;
            #pragma unroll 8
            for (int d = 0; d < D; d++) q += xs[tid * PAD + d] * v1_s[d];
            q_s[tid] = q;
        }
        // prefetch next chunk (overlaps both GEMMs)
        int nxt = ch + stride;
        if (nxt < nChunks) {
            int R1 = nxt * 128;
            #pragma unroll
            for (int u = 0; u < 8; u++) {
                int idx = tid + u * 512;
                int r = idx >> 5, c4 = idx & 31;
                int gr = R1 + r;
                pf[u] = (gr < N) ? ((const float4*)x)[(size_t)gr * 32 + c4]
                                 : make_float4(0.f, 0.f, 0.f, 0.f);
            }
        }
        __syncthreads();   // q_s visible

        // ---------------- GEMM1: z = x @ W1 (tf32 mma, A hi/lo split) ----------------
        float cfr[2][4][4];
        #pragma unroll
        for (int mi = 0; mi < 2; mi++)
            #pragma unroll
            for (int ni = 0; ni < 4; ni++)
                #pragma unroll
                for (int j = 0; j < 4; j++) cfr[mi][ni][j] = 0.0f;

        #pragma unroll 2
        for (int ks = 0; ks < 16; ks++) {
            int k0 = ks * 8;
            uint32_t ah[2][4], al[2][4];
            #pragma unroll
            for (int mi = 0; mi < 2; mi++) {
                int r = wm * 32 + mi * 16 + gid;
                float f0 = xs[r * PAD + k0 + tg];
                float f1 = xs[(r + 8) * PAD + k0 + tg];
                float f2 = xs[r * PAD + k0 + tg + 4];
                float f3 = xs[(r + 8) * PAD + k0 + tg + 4];
                ah[mi][0] = tf32cvt(f0); al[mi][0] = tf32cvt(f0 - __uint_as_float(ah[mi][0]));
                ah[mi][1] = tf32cvt(f1); al[mi][1] = tf32cvt(f1 - __uint_as_float(ah[mi][1]));
                ah[mi][2] = tf32cvt(f2); al[mi][2] = tf32cvt(f2 - __uint_as_float(ah[mi][2]));
                ah[mi][3] = tf32cvt(f3); al[mi][3] = tf32cvt(f3 - __uint_as_float(ah[mi][3]));
            }
            uint32_t bh[4][2];
            #pragma unroll
            for (int ni = 0; ni < 4; ni++) {
                int c = wn * 32 + ni * 8 + gid;
                bh[ni][0] = __float_as_uint(w1t[c * PAD + k0 + tg]);
                bh[ni][1] = __float_as_uint(w1t[c * PAD + k0 + tg + 4]);
            }
            #pragma unroll
            for (int mi = 0; mi < 2; mi++)
                #pragma unroll
                for (int ni = 0; ni < 4; ni++) {
                    mma_tf32(cfr[mi][ni], ah[mi][0], ah[mi][1], ah[mi][2], ah[mi][3], bh[ni][0], bh[ni][1]);
                    mma_tf32(cfr[mi][ni], al[mi][0], al[mi][1], al[mi][2], al[mi][3], bh[ni][0], bh[ni][1]);
                }
        }
        __syncthreads();   // all GEMM1 reads of xs complete

        // epilogue1: z = 0.5*acc + 0.5*q*a1 + b1; relu; store to xs
        #pragma unroll
        for (int mi = 0; mi < 2; mi++) {
            int r = wm * 32 + mi * 16 + gid;
            float qh0 = 0.5f * q_s[r], qh8 = 0.5f * q_s[r + 8];
            #pragma unroll
            for (int ni = 0; ni < 4; ni++) {
                int c = wn * 32 + ni * 8 + 2 * tg;
                float z00 = 0.5f * cfr[mi][ni][0] + qh0 * a1_s[c]     + be1_s[c];
                float z01 = 0.5f * cfr[mi][ni][1] + qh0 * a1_s[c + 1] + be1_s[c + 1];
                float z10 = 0.5f * cfr[mi][ni][2] + qh8 * a1_s[c]     + be1_s[c];
                float z11 = 0.5f * cfr[mi][ni][3] + qh8 * a1_s[c + 1] + be1_s[c + 1];
                *(float2*)&xs[r * PAD + c]       = make_float2(fmaxf(z00, 0.f), fmaxf(z01, 0.f));
                *(float2*)&xs[(r + 8) * PAD + c] = make_float2(fmaxf(z10, 0.f), fmaxf(z11, 0.f));
            }
        }
        __syncthreads();

        // ---------------- GEMM2: enh = relu(z) @ W2 ----------------
        #pragma unroll
        for (int mi = 0; mi < 2; mi++)
            #pragma unroll
            for (int ni = 0; ni < 4; ni++)
                #pragma unroll
                for (int j = 0; j < 4; j++) cfr[mi][ni][j] = 0.0f;

        #pragma unroll 2
        for (int ks = 0; ks < 16; ks++) {
            int k0 = ks * 8;
            uint32_t ah[2][4], al[2][4];
            #pragma unroll
            for (int mi = 0; mi < 2; mi++) {
                int r = wm * 32 + mi * 16 + gid;
                float f0 = xs[r * PAD + k0 + tg];
                float f1 = xs[(r + 8) * PAD + k0 + tg];
                float f2 = xs[r * PAD + k0 + tg + 4];
                float f3 = xs[(r + 8) * PAD + k0 + tg + 4];
                ah[mi][0] = tf32cvt(f0); al[mi][0] = tf32cvt(f0 - __uint_as_float(ah[mi][0]));
                ah[mi][1] = tf32cvt(f1); al[mi][1] = tf32cvt(f1 - __uint_as_float(ah[mi][1]));
                ah[mi][2] = tf32cvt(f2); al[mi][2] = tf32cvt(f2 - __uint_as_float(ah[mi][2]));
                ah[mi][3] = tf32cvt(f3); al[mi][3] = tf32cvt(f3 - __uint_as_float(ah[mi][3]));
            }
            uint32_t bh[4][2];
            #pragma unroll
            for (int ni = 0; ni < 4; ni++) {
                int c = wn * 32 + ni * 8 + gid;
                bh[ni][0] = __float_as_uint(w2t[c * PAD + k0 + tg]);
                bh[ni][1] = __float_as_uint(w2t[c * PAD + k0 + tg + 4]);
            }
            #pragma unroll
            for (int mi = 0; mi < 2; mi++)
                #pragma unroll
                for (int ni = 0; ni < 4; ni++) {
                    mma_tf32(cfr[mi][ni], ah[mi][0], ah[mi][1], ah[mi][2], ah[mi][3], bh[ni][0], bh[ni][1]);
                    mma_tf32(cfr[mi][ni], al[mi][0], al[mi][1], al[mi][2], al[mi][3], bh[ni][0], bh[ni][1]);
                }
        }

        // epilogue2: out = (acc + b2)*sc + 0.5*x + 0.5*q*v1  (x re-read from gmem/L2)
        #pragma unroll
        for (int mi = 0; mi < 2; mi++) {
            int r = wm * 32 + mi * 16 + gid;
            #pragma unroll
            for (int rr = 0; rr < 2; rr++) {
                int row = r + rr * 8;
                int gr = R0 + row;
                if (gr >= N) continue;
                float sc = sc_s[row], qh = 0.5f * q_s[row];
                #pragma unroll
                for (int ni = 0; ni < 4; ni++) {
                    int c = wn * 32 + ni * 8 + 2 * tg;
                    float e0 = cfr[mi][ni][rr * 2 + 0];
                    float e1 = cfr[mi][ni][rr * 2 + 1];
                    float2 xv = ((const float2*)x)[(size_t)gr * 64 + (c >> 1)];
                    float o0 = (e0 + be2_s[c])     * sc + 0.5f * xv.x + qh * v1_s[c];
                    float o1 = (e1 + be2_s[c + 1]) * sc + 0.5f * xv.y + qh * v1_s[c + 1];
                    ((float2*)out)[(size_t)gr * 64 + (c >> 1)] = make_float2(o0, o1);
                }
            }
        }
    }
}

// ---------------------------------------------------------------- launch
extern "C" void kernel_launch(void* const* d_in, const int* in_sizes, int n_in,
                              void* d_out, int out_size) {
    const float* x       = (const float*)d_in[0];
    const void*  ei      = d_in[1];
    const float* ew      = (const float*)d_in[2];
    const float* w_gcn   = (const float*)d_in[3];
    const float* b_gcn   = (const float*)d_in[4];
    const float* w_score = (const float*)d_in[5];
    const float* b_score = (const float*)d_in[6];
    const float* alpha   = (const float*)d_in[7];
    const float* beta    = (const float*)d_in[8];
    const float* w_e1    = (const float*)d_in[9];
    const float* b_e1    = (const float*)d_in[10];
    const float* w_e2    = (const float*)d_in[11];
    const float* b_e2    = (const float*)d_in[12];
    float* out = (float*)d_out;

    int N = in_sizes[0] / D;
    int E = in_sizes[2];
    int nChunks = (N + 127) / 128;
    int NB = (N + 255) / 256;
    int EB = (E + 255) / 256;
    int ZB = ((N > D * D ? N : D * D) + 255) / 256;
    int PB = (N * 32 + 255) / 256;

    const int SMG = 2 * 128 * PAD * 4;
    const int SMF = (3 * 128 * PAD + 256) * 4;
    const int SMS = D * D * 4;
    const int SMX = (D * PADE + 3 * 128) * 4;

    static int init_done = 0;
    static cudaStream_t s1;
    static cudaEvent_t evFork, evJoin;
    if (!init_done) {
        cudaFuncSetAttribute(k_G,       cudaFuncAttributeMaxDynamicSharedMemorySize, SMG);
        cudaFuncSetAttribute(k_sq,      cudaFuncAttributeMaxDynamicSharedMemorySize, SMS);
        cudaFuncSetAttribute(k_extract, cudaFuncAttributeMaxDynamicSharedMemorySize, SMX);
        cudaFuncSetAttribute(k_final3,  cudaFuncAttributeMaxDynamicSharedMemorySize, SMF);
        cudaStreamCreateWithFlags(&s1, cudaStreamNonBlocking);
        cudaEventCreateWithFlags(&evFork, cudaEventDisableTiming);
        cudaEventCreateWithFlags(&evJoin, cudaEventDisableTiming);
        init_done = 1;
    }

    k_pre<<<ZB + 2, 256>>>((const long long*)ei, E, N, w_gcn, b_gcn, w_score, b_score, ZB);  // launch 1

    cudaEventRecord(evFork, 0);
    cudaStreamWaitEvent(s1, evFork, 0);

    // s1 chain first four launches, then k_G as launch #6 (profiled by ncu -s 5 -c 1)
    k_deg<<<EB, 256, 0, s1>>>(ei, E);                       // 2
    k_p<<<PB, 256, 0, s1>>>(x, N);                          // 3
    k_dinv<<<NB, 256, 0, s1>>>(N);                          // 4
    k_edge<<<EB, 256, 0, s1>>>(ei, E);                      // 5
    k_G<<<148, 512, SMG>>>(x, N, nChunks);                  // 6  <- profiled
    k_scores<<<NB, 256, 0, s1>>>(N);
    k_gate<<<EB, 256, 0, s1>>>(ei, ew, alpha, beta, out + (size_t)N * D, E);
    cudaEventRecord(evJoin, s1);

    for (int it = 0; it < NSQ; it++)
        k_sq<<<8, 256, SMS>>>(it);
    k_extract<<<1, 128, SMX>>>(w_e1);

    cudaStreamWaitEvent(0, evJoin, 0);
    k_final3<<<148, 512, SMF>>>(x, b_e1, b_e2, w_e1, w_e2, out, N, nChunks);
}

// round 6
// speedup vs baseline: 1.5539x; 1.2860x over previous
#include <cuda_runtime.h>
#include <math.h>
#include <stdint.h>

#define D 128
#define PAD 132            // k_final smem row pitch (floats)
#define PADG 136           // k_G pitch: mod 32 == 8 -> conflict-free mma fragment loads
#define PADE 129
#define NMAX 65536
#define NSQ 10
#define NREF 5
#define PWB 16             // k_power blocks

static __device__ int   g_degi[NMAX];
static __device__ float g_dinv[NMAX];
static __device__ float g_p[NMAX];
static __device__ float g_sacc[NMAX];
static __device__ float g_scores[NMAX];
static __device__ __align__(16) float g_G[D * D];
static __device__ __align__(16) float g_Ea[D * D];
static __device__ __align__(16) float g_Eb[D * D];
static __device__ float g_v1[D];
static __device__ float g_a1[D];
static __device__ float g_wv[D];
static __device__ float g_bg;
static __device__ int   g_i32;
static __device__ int   g_bar;

// ---------------------------------------------------------------- utilities
__device__ __forceinline__ void load_edge(const void* ei, int E, int e, int& s, int& t) {
    if (g_i32) {
        const int* p = (const int*)ei;
        s = p[e]; t = p[E + e];
    } else {
        const long long* p = (const long long*)ei;
        s = (int)p[e]; t = (int)p[E + e];
    }
}

__device__ __forceinline__ float sigmoidf_(float z) {
    return 1.0f / (1.0f + expf(-z));
}

__device__ __forceinline__ unsigned smem_u32(const void* p) {
    return (unsigned)__cvta_generic_to_shared(p);
}
__device__ __forceinline__ void cp16(unsigned s, const void* g) {
    asm volatile("cp.async.cg.shared.global [%0], [%1], 16;\n" :: "r"(s), "l"(g));
}
#define CP_COMMIT() asm volatile("cp.async.commit_group;\n" ::)
#define CP_WAIT(n)  asm volatile("cp.async.wait_group %0;\n" :: "n"(n))

__device__ __forceinline__ uint32_t tf32cvt(float f) {
    uint32_t u;
    asm("cvt.rna.tf32.f32 %0, %1;" : "=r"(u) : "f"(f));
    return u;
}

__device__ __forceinline__ void mma_tf32(float* c, uint32_t a0, uint32_t a1, uint32_t a2, uint32_t a3,
                                         uint32_t b0, uint32_t b1) {
    asm volatile("mma.sync.aligned.m16n8k8.row.col.f32.tf32.tf32.f32 "
                 "{%0,%1,%2,%3}, {%4,%5,%6,%7}, {%8,%9}, {%0,%1,%2,%3};"
                 : "+f"(c[0]), "+f"(c[1]), "+f"(c[2]), "+f"(c[3])
                 : "r"(a0), "r"(a1), "r"(a2), "r"(a3), "r"(b0), "r"(b1));
}

// ---------------------------------------------------------------- fused prologue
__global__ void k_pre(const long long* ei, int E, int N,
                      const float* __restrict__ wg, const float* __restrict__ bgc,
                      const float* __restrict__ ws, const float* __restrict__ bs, int ZB) {
    int b = blockIdx.x, t = threadIdx.x;
    if (b < ZB) {
        int i = b * 256 + t;
        if (i < N) g_degi[i] = 0;
        if (i < D * D) g_G[i] = 0.0f;
        if (i == 0 && b == 0) g_bar = 0;
    } else if (b == ZB) {
        __shared__ int flag;
        if (t == 0) flag = 0;
        __syncthreads();
        int n = E < 1024 ? E : 1024;
        for (int e = t; e < n; e += 256)
            if ((unsigned long long)ei[e] >= (unsigned long long)N) flag = 1;
        __syncthreads();
        if (t == 0) g_i32 = flag;
    } else {
        __shared__ float wss[D];
        if (t < D) wss[t] = ws[t];
        __syncthreads();
        if (t < D) {
            float s = 0.0f;
            #pragma unroll 8
            for (int m = 0; m < D; m++) s += wg[t * D + m] * wss[m];
            g_wv[t] = s;
        }
        if (t == 0) {
            float bsum = bs[0];
            for (int m = 0; m < D; m++) bsum += bgc[m] * wss[m];
            g_bg = bsum;
        }
    }
}

// ---------------------------------------------------------------- edge/score chain (s1)
__global__ void k_p(const float* __restrict__ x, int N) {
    int w = (blockIdx.x * blockDim.x + threadIdx.x) >> 5;
    int lane = threadIdx.x & 31;
    if (w >= N) return;
    float4 xv = ((const float4*)x)[(size_t)w * 32 + lane];
    float4 wv = *(const float4*)&g_wv[lane * 4];
    float s = xv.x * wv.x + xv.y * wv.y + xv.z * wv.z + xv.w * wv.w;
    #pragma unroll
    for (int o = 16; o; o >>= 1) s += __shfl_xor_sync(0xffffffffu, s, o);
    if (lane == 0) g_p[w] = s;
}

__global__ void k_deg(const void* ei, int E) {
    int e = blockIdx.x * 256 + threadIdx.x;
    if (e >= E) return;
    int t = g_i32 ? ((const int*)ei)[E + e] : (int)((const long long*)ei)[E + e];
    atomicAdd(&g_degi[t], 1);
}

__global__ void k_dinv(int N) {
    int i = blockIdx.x * 256 + threadIdx.x;
    if (i >= N) return;
    float di = rsqrtf((float)(g_degi[i] + 1));
    g_dinv[i] = di;
    g_sacc[i] = di * di * g_p[i];
}

__global__ void k_edge(const void* ei, int E) {
    int e = blockIdx.x * 256 + threadIdx.x;
    if (e >= E) return;
    int s, t; load_edge(ei, E, e, s, t);
    atomicAdd(&g_sacc[t], g_dinv[s] * g_dinv[t] * g_p[s]);
}

__global__ void k_scores(int N) {
    int i = blockIdx.x * 256 + threadIdx.x;
    if (i >= N) return;
    g_scores[i] = sigmoidf_(g_sacc[i] + g_bg);
}

__global__ void k_gate(const void* ei, const float* __restrict__ ew,
                       const float* __restrict__ al, const float* __restrict__ be,
                       float* __restrict__ out, int E) {
    int e = blockIdx.x * 256 + threadIdx.x;
    if (e >= E) return;
    int s, t; load_edge(ei, E, e, s, t);
    float z = al[0] * (g_scores[s] + g_scores[t]) + be[0];
    out[e] = ew[e] * sigmoidf_(z);
}

// ---------------------------------------------------------------- Gram: tf32 mma, 3-pass hi/lo split
// G[i][j] = sum_r X[r][i]*X[r][j]; A row-major [i][k=r], B col-major [j][k=r] both read from xs.
__global__ __launch_bounds__(512, 1) void k_G(const float* __restrict__ x, int N, int nChunks) {
    extern __shared__ float sm[];
    float* bufs[2] = { sm, sm + 128 * PADG };
    int tid = threadIdx.x;
    int wid = tid >> 5, lane = tid & 31;
    int wm = wid >> 2, wn = wid & 3;
    int gid = lane >> 2, tg = lane & 3;
    int m0 = wm * 32, n0 = wn * 32;
    int stride = gridDim.x;

    float acc[2][4][4];
    #pragma unroll
    for (int mi = 0; mi < 2; mi++)
        #pragma unroll
        for (int ni = 0; ni < 4; ni++)
            #pragma unroll
            for (int j = 0; j < 4; j++) acc[mi][ni][j] = 0.0f;

    int ch = blockIdx.x;
    if (ch < nChunks) {
        int R0 = ch * 128;
        if (R0 + 128 <= N) {
            #pragma unroll
            for (int u = 0; u < 8; u++) {
                int idx = tid + u * 512;
                int r = idx >> 5, c4 = idx & 31;
                cp16(smem_u32(&bufs[0][r * PADG + c4 * 4]), &x[((size_t)(R0 + r)) * 128 + c4 * 4]);
            }
        } else {
            #pragma unroll
            for (int u = 0; u < 8; u++) {
                int idx = tid + u * 512;
                int r = idx >> 5, c4 = idx & 31;
                int gr = R0 + r;
                float4 v = (gr < N) ? ((const float4*)x)[(size_t)gr * 32 + c4]
                                    : make_float4(0.f, 0.f, 0.f, 0.f);
                *(float4*)&bufs[0][r * PADG + c4 * 4] = v;
            }
        }
        CP_COMMIT();
    }

    int cur = 0;
    for (; ch < nChunks; ch += stride) {
        int nxt = ch + stride;
        if (nxt < nChunks) {
            float* bn = bufs[cur ^ 1];
            int R0 = nxt * 128;
            if (R0 + 128 <= N) {
                #pragma unroll
                for (int u = 0; u < 8; u++) {
                    int idx = tid + u * 512;
                    int r = idx >> 5, c4 = idx & 31;
                    cp16(smem_u32(&bn[r * PADG + c4 * 4]), &x[((size_t)(R0 + r)) * 128 + c4 * 4]);
                }
            } else {
                #pragma unroll
                for (int u = 0; u < 8; u++) {
                    int idx = tid + u * 512;
                    int r = idx >> 5, c4 = idx & 31;
                    int gr = R0 + r;
                    float4 v = (gr < N) ? ((const float4*)x)[(size_t)gr * 32 + c4]
                                        : make_float4(0.f, 0.f, 0.f, 0.f);
                    *(float4*)&bn[r * PADG + c4 * 4] = v;
                }
            }
            CP_COMMIT();
            CP_WAIT(1);
        } else {
            CP_WAIT(0);
        }
        __syncthreads();
        const float* bc = bufs[cur];

        #pragma unroll 2
        for (int ks = 0; ks < 16; ks++) {
            int k0 = ks * 8;
            uint32_t ah[2][4], al[2][4];
            #pragma unroll
            for (int mi = 0; mi < 2; mi++) {
                int i0 = m0 + mi * 16 + gid;
                float f0 = bc[(k0 + tg) * PADG + i0];
                float f1 = bc[(k0 + tg) * PADG + i0 + 8];
                float f2 = bc[(k0 + tg + 4) * PADG + i0];
                float f3 = bc[(k0 + tg + 4) * PADG + i0 + 8];
                ah[mi][0] = tf32cvt(f0); al[mi][0] = tf32cvt(f0 - __uint_as_float(ah[mi][0]));
                ah[mi][1] = tf32cvt(f1); al[mi][1] = tf32cvt(f1 - __uint_as_float(ah[mi][1]));
                ah[mi][2] = tf32cvt(f2); al[mi][2] = tf32cvt(f2 - __uint_as_float(ah[mi][2]));
                ah[mi][3] = tf32cvt(f3); al[mi][3] = tf32cvt(f3 - __uint_as_float(ah[mi][3]));
            }
            uint32_t bh[4][2], bl[4][2];
            #pragma unroll
            for (int ni = 0; ni < 4; ni++) {
                int j0 = n0 + ni * 8 + gid;
                float g0 = bc[(k0 + tg) * PADG + j0];
                float g1 = bc[(k0 + tg + 4) * PADG + j0];
                bh[ni][0] = tf32cvt(g0); bl[ni][0] = tf32cvt(g0 - __uint_as_float(bh[ni][0]));
                bh[ni][1] = tf32cvt(g1); bl[ni][1] = tf32cvt(g1 - __uint_as_float(bh[ni][1]));
            }
            #pragma unroll
            for (int mi = 0; mi < 2; mi++)
                #pragma unroll
                for (int ni = 0; ni < 4; ni++) {
                    mma_tf32(acc[mi][ni], ah[mi][0], ah[mi][1], ah[mi][2], ah[mi][3], bh[ni][0], bh[ni][1]);
                    mma_tf32(acc[mi][ni], ah[mi][0], ah[mi][1], ah[mi][2], ah[mi][3], bl[ni][0], bl[ni][1]);
                    mma_tf32(acc[mi][ni], al[mi][0], al[mi][1], al[mi][2], al[mi][3], bh[ni][0], bh[ni][1]);
                }
        }
        cur ^= 1;
        __syncthreads();
    }
    #pragma unroll
    for (int mi = 0; mi < 2; mi++)
        #pragma unroll
        for (int ni = 0; ni < 4; ni++) {
            int r = m0 + mi * 16 + gid, c = n0 + ni * 8 + 2 * tg;
            atomicAdd(&g_G[r * D + c],           acc[mi][ni][0]);
            atomicAdd(&g_G[r * D + c + 1],       acc[mi][ni][1]);
            atomicAdd(&g_G[(r + 8) * D + c],     acc[mi][ni][2]);
            atomicAdd(&g_G[(r + 8) * D + c + 1], acc[mi][ni][3]);
        }
}

// ---------------------------------------------------------------- fused power iteration + extract
// 16 blocks x 1024 threads, software global barrier; NSQ normalized squarings (fp32),
// then block 0 extracts v1 (dominant column + NREF matvecs) and computes a1.
__global__ __launch_bounds__(1024, 1) void k_power(const float* __restrict__ w1) {
    extern __shared__ float sm[];
    float* As = sm;                        // pitch PAD (132) in sq phase; PADE (129) in extract
    int tid = threadIdx.x;
    int ty = tid >> 7;                     // 0..7
    int tx = tid & 127;
    int wid = tid >> 5, lane = tid & 31;
    int r = blockIdx.x * 8 + ty;
    __shared__ float redm[32];

    for (int it = 0; it < NSQ; it++) {
        const float* in = (it == 0) ? g_G : ((it & 1) ? g_Ea : g_Eb);
        float* outp = (it & 1) ? g_Eb : g_Ea;
        float m = 0.0f;
        #pragma unroll
        for (int u = 0; u < 4; u++) {
            int idx = tid + u * 1024;      // 4096 float4
            int rr = idx >> 5, c4 = idx & 31;
            float4 v = ((const float4*)in)[idx];
            *(float4*)&As[rr * PAD + c4 * 4] = v;
            m = fmaxf(m, fmaxf(fmaxf(fabsf(v.x), fabsf(v.y)), fmaxf(fabsf(v.z), fabsf(v.w))));
        }
        #pragma unroll
        for (int o = 16; o; o >>= 1) m = fmaxf(m, __shfl_xor_sync(0xffffffffu, m, o));
        if (lane == 0) redm[wid] = m;
        __syncthreads();
        if (tid < 32) {
            float mm = redm[tid];
            #pragma unroll
            for (int o = 16; o; o >>= 1) mm = fmaxf(mm, __shfl_xor_sync(0xffffffffu, mm, o));
            if (tid == 0) redm[0] = mm;
        }
        __syncthreads();
        float inv = 1.0f / redm[0];
        float inv2 = inv * inv;

        float acc = 0.0f;
        #pragma unroll 8
        for (int k = 0; k < D; k++) acc += As[r * PAD + k] * As[k * PAD + tx];
        outp[r * D + tx] = acc * inv2;

        __threadfence();
        __syncthreads();
        if (tid == 0) {
            atomicAdd(&g_bar, 1);
            int target = PWB * (it + 1);
            while (*(volatile int*)&g_bar < target) { }
        }
        __syncthreads();
    }

    if (blockIdx.x != 0) return;

    // ------- extract (block 0 only; all 1024 threads participate in syncs) -------
    float* vv = sm + D * PADE;
    float* uu = vv + D;
    float* red = uu + D;
    __shared__ int redi[128];
    __shared__ int jm;
    const float* P = (NSQ & 1) ? g_Eb : g_Ea;
    for (int idx = tid; idx < D * D; idx += 1024) {
        int rr = idx >> 7, c = idx & 127;
        As[rr * PADE + c] = P[idx];
    }
    __syncthreads();
    if (tid < D) { red[tid] = As[tid * PADE + tid]; redi[tid] = tid; }
    __syncthreads();
    for (int s = 64; s > 0; s >>= 1) {
        if (tid < s && red[tid + s] > red[tid]) { red[tid] = red[tid + s]; redi[tid] = redi[tid + s]; }
        __syncthreads();
    }
    if (tid == 0) jm = redi[0];
    __syncthreads();
    if (tid < D) vv[tid] = As[jm * PADE + tid];
    __syncthreads();

    for (int itr = 0; itr < NREF; itr++) {
        if (tid < D) {
            float s = 0.0f;
            #pragma unroll 8
            for (int c = 0; c < D; c++) s += As[tid * PADE + c] * vv[c];
            uu[tid] = s;
            red[tid] = s * s;
        }
        __syncthreads();
        for (int r2 = 64; r2 > 0; r2 >>= 1) {
            if (tid < r2) red[tid] += red[tid + r2];
            __syncthreads();
        }
        float invn = rsqrtf(fmaxf(red[0], 1e-30f));
        __syncthreads();
        if (tid < D) vv[tid] = uu[tid] * invn;
        __syncthreads();
    }

    if (tid < D) {
        g_v1[tid] = vv[tid];
        float a = 0.0f;
        #pragma unroll 8
        for (int d2 = 0; d2 < D; d2++) a += vv[d2] * w1[d2 * D + tid];
        g_a1[tid] = a;
    }
}

// ---------------------------------------------------------------- fused enhancer, tf32 mma
// out = (relu(0.5 x@W1 + 0.5 q a1^T + b1) @ W2 + b2)*scores + 0.5 x + 0.5 q v1^T
// GEMM1: A hi/lo split (2-pass). epi1 stores relu(z) PRE-ROUNDED tf32 -> GEMM2 single-pass, no cvt.
__global__ __launch_bounds__(512, 1) void k_final3(const float* __restrict__ x,
                        const float* __restrict__ b1, const float* __restrict__ b2,
                        const float* __restrict__ w1, const float* __restrict__ w2,
                        float* __restrict__ out, int N, int nChunks) {
    extern __shared__ float sm[];
    float* xs  = sm;                       // x chunk -> relu(z) tf32, 128*PAD
    float* w1t = sm + 128 * PAD;           // W1^T tf32, [n][k]
    float* w2t = w1t + 128 * PAD;
    float* q_s = w2t + 128 * PAD;
    float* sc_s = q_s + 128;
    __shared__ float v1_s[D], a1_s[D], be1_s[D], be2_s[D];

    int tid = threadIdx.x;
    int wid = tid >> 5, lane = tid & 31;
    int wm = wid >> 2, wn = wid & 3;
    int gid = lane >> 2, tg = lane & 3;
    int stride = gridDim.x;

    for (int idx = tid; idx < D * D; idx += 512) {
        int k = idx >> 7, n = idx & 127;
        w1t[n * PAD + k] = __uint_as_float(tf32cvt(w1[idx]));
        w2t[n * PAD + k] = __uint_as_float(tf32cvt(w2[idx]));
    }
    if (tid < D) {
        v1_s[tid] = g_v1[tid]; a1_s[tid] = g_a1[tid];
        be1_s[tid] = b1[tid];  be2_s[tid] = b2[tid];
    }

    float4 pf[8];
    int ch = blockIdx.x;
    if (ch < nChunks) {
        int R0 = ch * 128;
        #pragma unroll
        for (int u = 0; u < 8; u++) {
            int idx = tid + u * 512;
            int r = idx >> 5, c4 = idx & 31;
            int gr = R0 + r;
            pf[u] = (gr < N) ? ((const float4*)x)[(size_t)gr * 32 + c4]
                             : make_float4(0.f, 0.f, 0.f, 0.f);
        }
    }

    for (; ch < nChunks; ch += stride) {
        int R0 = ch * 128;
        __syncthreads();
        #pragma unroll
        for (int u = 0; u < 8; u++) {
            int idx = tid + u * 512;
            int r = idx >> 5, c4 = idx & 31;
            *(float4*)&xs[r * PAD + c4 * 4] = pf[u];
        }
        if (tid < 128) sc_s[tid] = (R0 + tid < N) ? g_scores[R0 + tid] : 0.0f;
        __syncthreads();
        if (tid < 128) {
            float q = 0.0f;
            #pragma unroll 8
            for (int d = 0; d < D; d++) q += xs[tid * PAD + d] * v1_s[d];
            q_s[tid] = q;
        }
        int nxt = ch + stride;
        if (nxt < nChunks) {
            int R1 = nxt * 128;
            #pragma unroll
            for (int u = 0; u < 8; u++) {
                int idx = tid + u * 512;
                int r = idx >> 5, c4 = idx & 31;
                int gr = R1 + r;
                pf[u] = (gr < N) ? ((const float4*)x)[(size_t)gr * 32 + c4]
                                 : make_float4(0.f, 0.f, 0.f, 0.f);
            }
        }
        __syncthreads();

        // ---------------- GEMM1: z = x @ W1 (tf32 mma, A hi/lo split) ----------------
        float cfr[2][4][4];
        #pragma unroll
        for (int mi = 0; mi < 2; mi++)
            #pragma unroll
            for (int ni = 0; ni < 4; ni++)
                #pragma unroll
                for (int j = 0; j < 4; j++) cfr[mi][ni][j] = 0.0f;

        #pragma unroll 2
        for (int ks = 0; ks < 16; ks++) {
            int k0 = ks * 8;
            uint32_t ah[2][4], al[2][4];
            #pragma unroll
            for (int mi = 0; mi < 2; mi++) {
                int r = wm * 32 + mi * 16 + gid;
                float f0 = xs[r * PAD + k0 + tg];
                float f1 = xs[(r + 8) * PAD + k0 + tg];
                float f2 = xs[r * PAD + k0 + tg + 4];
                float f3 = xs[(r + 8) * PAD + k0 + tg + 4];
                ah[mi][0] = tf32cvt(f0); al[mi][0] = tf32cvt(f0 - __uint_as_float(ah[mi][0]));
                ah[mi][1] = tf32cvt(f1); al[mi][1] = tf32cvt(f1 - __uint_as_float(ah[mi][1]));
                ah[mi][2] = tf32cvt(f2); al[mi][2] = tf32cvt(f2 - __uint_as_float(ah[mi][2]));
                ah[mi][3] = tf32cvt(f3); al[mi][3] = tf32cvt(f3 - __uint_as_float(ah[mi][3]));
            }
            uint32_t bh[4][2];
            #pragma unroll
            for (int ni = 0; ni < 4; ni++) {
                int c = wn * 32 + ni * 8 + gid;
                bh[ni][0] = __float_as_uint(w1t[c * PAD + k0 + tg]);
                bh[ni][1] = __float_as_uint(w1t[c * PAD + k0 + tg + 4]);
            }
            #pragma unroll
            for (int mi = 0; mi < 2; mi++)
                #pragma unroll
                for (int ni = 0; ni < 4; ni++) {
                    mma_tf32(cfr[mi][ni], ah[mi][0], ah[mi][1], ah[mi][2], ah[mi][3], bh[ni][0], bh[ni][1]);
                    mma_tf32(cfr[mi][ni], al[mi][0], al[mi][1], al[mi][2], al[mi][3], bh[ni][0], bh[ni][1]);
                }
        }
        __syncthreads();

        // epilogue1: z = 0.5*acc + 0.5*q*a1 + b1; relu; store PRE-ROUNDED tf32
        #pragma unroll
        for (int mi = 0; mi < 2; mi++) {
            int r = wm * 32 + mi * 16 + gid;
            float qh0 = 0.5f * q_s[r], qh8 = 0.5f * q_s[r + 8];
            #pragma unroll
            for (int ni = 0; ni < 4; ni++) {
                int c = wn * 32 + ni * 8 + 2 * tg;
                float z00 = 0.5f * cfr[mi][ni][0] + qh0 * a1_s[c]     + be1_s[c];
                float z01 = 0.5f * cfr[mi][ni][1] + qh0 * a1_s[c + 1] + be1_s[c + 1];
                float z10 = 0.5f * cfr[mi][ni][2] + qh8 * a1_s[c]     + be1_s[c];
                float z11 = 0.5f * cfr[mi][ni][3] + qh8 * a1_s[c + 1] + be1_s[c + 1];
                xs[r * PAD + c]           = __uint_as_float(tf32cvt(fmaxf(z00, 0.f)));
                xs[r * PAD + c + 1]       = __uint_as_float(tf32cvt(fmaxf(z01, 0.f)));
                xs[(r + 8) * PAD + c]     = __uint_as_float(tf32cvt(fmaxf(z10, 0.f)));
                xs[(r + 8) * PAD + c + 1] = __uint_as_float(tf32cvt(fmaxf(z11, 0.f)));
            }
        }
        __syncthreads();

        // ---------------- GEMM2: enh = relu(z) @ W2 (single pass, A pre-rounded) ----------------
        #pragma unroll
        for (int mi = 0; mi < 2; mi++)
            #pragma unroll
            for (int ni = 0; ni < 4; ni++)
                #pragma unroll
                for (int j = 0; j < 4; j++) cfr[mi][ni][j] = 0.0f;

        #pragma unroll 2
        for (int ks = 0; ks < 16; ks++) {
            int k0 = ks * 8;
            uint32_t a2[2][4];
            #pragma unroll
            for (int mi = 0; mi < 2; mi++) {
                int r = wm * 32 + mi * 16 + gid;
                a2[mi][0] = __float_as_uint(xs[r * PAD + k0 + tg]);
                a2[mi][1] = __float_as_uint(xs[(r + 8) * PAD + k0 + tg]);
                a2[mi][2] = __float_as_uint(xs[r * PAD + k0 + tg + 4]);
                a2[mi][3] = __float_as_uint(xs[(r + 8) * PAD + k0 + tg + 4]);
            }
            uint32_t bh[4][2];
            #pragma unroll
            for (int ni = 0; ni < 4; ni++) {
                int c = wn * 32 + ni * 8 + gid;
                bh[ni][0] = __float_as_uint(w2t[c * PAD + k0 + tg]);
                bh[ni][1] = __float_as_uint(w2t[c * PAD + k0 + tg + 4]);
            }
            #pragma unroll
            for (int mi = 0; mi < 2; mi++)
                #pragma unroll
                for (int ni = 0; ni < 4; ni++)
                    mma_tf32(cfr[mi][ni], a2[mi][0], a2[mi][1], a2[mi][2], a2[mi][3], bh[ni][0], bh[ni][1]);
        }

        // epilogue2
        #pragma unroll
        for (int mi = 0; mi < 2; mi++) {
            int r = wm * 32 + mi * 16 + gid;
            #pragma unroll
            for (int rr = 0; rr < 2; rr++) {
                int row = r + rr * 8;
                int gr = R0 + row;
                if (gr >= N) continue;
                float sc = sc_s[row], qh = 0.5f * q_s[row];
                #pragma unroll
                for (int ni = 0; ni < 4; ni++) {
                    int c = wn * 32 + ni * 8 + 2 * tg;
                    float e0 = cfr[mi][ni][rr * 2 + 0];
                    float e1 = cfr[mi][ni][rr * 2 + 1];
                    float2 xv = ((const float2*)x)[(size_t)gr * 64 + (c >> 1)];
                    float o0 = (e0 + be2_s[c])     * sc + 0.5f * xv.x + qh * v1_s[c];
                    float o1 = (e1 + be2_s[c + 1]) * sc + 0.5f * xv.y + qh * v1_s[c + 1];
                    ((float2*)out)[(size_t)gr * 64 + (c >> 1)] = make_float2(o0, o1);
                }
            }
        }
    }
}

// ---------------------------------------------------------------- launch
extern "C" void kernel_launch(void* const* d_in, const int* in_sizes, int n_in,
                              void* d_out, int out_size) {
    const float* x       = (const float*)d_in[0];
    const void*  ei      = d_in[1];
    const float* ew      = (const float*)d_in[2];
    const float* w_gcn   = (const float*)d_in[3];
    const float* b_gcn   = (const float*)d_in[4];
    const float* w_score = (const float*)d_in[5];
    const float* b_score = (const float*)d_in[6];
    const float* alpha   = (const float*)d_in[7];
    const float* beta    = (const float*)d_in[8];
    const float* w_e1    = (const float*)d_in[9];
    const float* b_e1    = (const float*)d_in[10];
    const float* w_e2    = (const float*)d_in[11];
    const float* b_e2    = (const float*)d_in[12];
    float* out = (float*)d_out;

    int N = in_sizes[0] / D;
    int E = in_sizes[2];
    int nChunks = (N + 127) / 128;
    int NB = (N + 255) / 256;
    int EB = (E + 255) / 256;
    int ZB = ((N > D * D ? N : D * D) + 255) / 256;
    int PB = (N * 32 + 255) / 256;

    const int SMG = 2 * 128 * PADG * 4;
    const int SMF = (3 * 128 * PAD + 256) * 4;
    const int SMP = (128 * PAD) * 4;          // == 128*PADE + 3*128 exactly
    static int init_done = 0;
    static cudaStream_t s1;
    static cudaEvent_t evFork, evJoin;
    if (!init_done) {
        cudaFuncSetAttribute(k_G,      cudaFuncAttributeMaxDynamicSharedMemorySize, SMG);
        cudaFuncSetAttribute(k_power,  cudaFuncAttributeMaxDynamicSharedMemorySize, SMP);
        cudaFuncSetAttribute(k_final3, cudaFuncAttributeMaxDynamicSharedMemorySize, SMF);
        cudaStreamCreateWithFlags(&s1, cudaStreamNonBlocking);
        cudaEventCreateWithFlags(&evFork, cudaEventDisableTiming);
        cudaEventCreateWithFlags(&evJoin, cudaEventDisableTiming);
        init_done = 1;
    }

    k_pre<<<ZB + 2, 256>>>((const long long*)ei, E, N, w_gcn, b_gcn, w_score, b_score, ZB);

    cudaEventRecord(evFork, 0);
    cudaStreamWaitEvent(s1, evFork, 0);

    k_deg<<<EB, 256, 0, s1>>>(ei, E);
    k_p<<<PB, 256, 0, s1>>>(x, N);
    k_dinv<<<NB, 256, 0, s1>>>(N);
    k_edge<<<EB, 256, 0, s1>>>(ei, E);
    k_scores<<<NB, 256, 0, s1>>>(N);
    k_gate<<<EB, 256, 0, s1>>>(ei, ew, alpha, beta, out + (size_t)N * D, E);
    cudaEventRecord(evJoin, s1);

    k_G<<<148, 512, SMG>>>(x, N, nChunks);
    k_power<<<PWB, 1024, SMP>>>(w_e1);

    cudaStreamWaitEvent(0, evJoin, 0);
    k_final3<<<148, 512, SMF>>>(x, b_e1, b_e2, w_e1, w_e2, out, N, nChunks);
}